// round 4
// baseline (speedup 1.0000x reference)
#include <cuda_runtime.h>
#include <cuda_bf16.h>
#include <math.h>

// Problem constants
#define BATCH 2
#define SEQ   2048
#define TOK   (BATCH*SEQ)     // 4096
#define HID   768
#define INNER 1536
#define NSTATE 16
#define KCONV 4
#define XPW   (2*INNER)       // 3072
#define PJW   (2*NSTATE+INNER)// 1568

// -------- scratch (device globals: allocation-free) --------
__device__ float g_xn[TOK*HID];
__device__ float g_xp[TOK*XPW];
__device__ float g_u [TOK*INNER];
__device__ float g_pj[TOK*PJW];
__device__ float g_y1[TOK*INNER];
__device__ float g_y2[TOK*INNER];

// ===================== LayerNorm =====================
__global__ __launch_bounds__(256) void ln_kernel(
    const float* __restrict__ x, const float* __restrict__ w,
    const float* __restrict__ b, float* __restrict__ o)
{
    int t = blockIdx.x;
    const float* xr = x + (size_t)t*HID;
    float s = 0.f, s2 = 0.f;
    for (int i = threadIdx.x; i < HID; i += 256) {
        float v = xr[i]; s += v; s2 += v*v;
    }
    __shared__ float red0[32], red1[32];
    #pragma unroll
    for (int off = 16; off > 0; off >>= 1) {
        s  += __shfl_down_sync(0xffffffffu, s,  off);
        s2 += __shfl_down_sync(0xffffffffu, s2, off);
    }
    int wid = threadIdx.x >> 5, lid = threadIdx.x & 31;
    if (lid == 0) { red0[wid] = s; red1[wid] = s2; }
    __syncthreads();
    if (wid == 0) {
        s  = (lid < 8) ? red0[lid] : 0.f;
        s2 = (lid < 8) ? red1[lid] : 0.f;
        #pragma unroll
        for (int off = 4; off > 0; off >>= 1) {
            s  += __shfl_down_sync(0xffffffffu, s,  off);
            s2 += __shfl_down_sync(0xffffffffu, s2, off);
        }
        if (lid == 0) { red0[0] = s; red1[0] = s2; }
    }
    __syncthreads();
    float mu  = red0[0] * (1.f/HID);
    float var = red1[0] * (1.f/HID) - mu*mu;
    float inv = rsqrtf(var + 1e-5f);
    float* orow = o + (size_t)t*HID;
    for (int i = threadIdx.x; i < HID; i += 256) {
        float v = xr[i];
        orow[i] = (v - mu) * inv * w[i] + b[i];
    }
}

// ===================== SGEMM 128x128x16, 8x8/thread =====================
// C[M,N] = A[M,K] @ B[K,N]; optional epilogues:
//   EP=0 none; EP=1: C *= silu(E[row*lde+eoff+col]); EP=2: C += E[row*lde+col]
// Requires: M%128==0, K%16==0, N%4==0 (N bound guarded).
template<int EP>
__global__ __launch_bounds__(256) void sgemm_k(
    const float* __restrict__ A, const float* __restrict__ B, float* __restrict__ C,
    int M, int N, int K,
    const float* __restrict__ E, int lde, int eoff)
{
    __shared__ float As[16][128];
    __shared__ float Bs[16][128];
    const int tid = threadIdx.x;
    const int tx  = tid & 15;     // 0..15 -> N
    const int ty  = tid >> 4;     // 0..15 -> M
    const int bm  = blockIdx.y * 128;
    const int bn  = blockIdx.x * 128;

    float acc[8][8];
    #pragma unroll
    for (int i = 0; i < 8; i++)
        #pragma unroll
        for (int j = 0; j < 8; j++) acc[i][j] = 0.f;

    const int nk = K >> 4;
    for (int kt = 0; kt < nk; kt++) {
        const int k0 = kt << 4;
        // ---- A tile: 128 rows x 16 cols (512 float4) ----
        #pragma unroll
        for (int j = 0; j < 2; j++) {
            int q  = tid*2 + j;
            int r  = q >> 2;          // row 0..127
            int cv = (q & 3) << 2;    // 0,4,8,12
            float4 v = *reinterpret_cast<const float4*>(
                A + (size_t)(bm + r)*K + k0 + cv);
            As[cv+0][r] = v.x; As[cv+1][r] = v.y;
            As[cv+2][r] = v.z; As[cv+3][r] = v.w;
        }
        // ---- B tile: 16 rows x 128 cols (512 float4) ----
        #pragma unroll
        for (int j = 0; j < 2; j++) {
            int q  = tid*2 + j;
            int kr = q >> 5;          // 0..15
            int nc = (q & 31) << 2;   // 0..124
            float4 v;
            int ncol = bn + nc;
            if (ncol < N)
                v = *reinterpret_cast<const float4*>(
                    B + (size_t)(k0 + kr)*N + ncol);
            else
                v = make_float4(0.f,0.f,0.f,0.f);
            *reinterpret_cast<float4*>(&Bs[kr][nc]) = v;
        }
        __syncthreads();
        #pragma unroll
        for (int k = 0; k < 16; k++) {
            float a[8], bb[8];
            *reinterpret_cast<float4*>(&a[0])  = *reinterpret_cast<const float4*>(&As[k][ty*8+0]);
            *reinterpret_cast<float4*>(&a[4])  = *reinterpret_cast<const float4*>(&As[k][ty*8+4]);
            *reinterpret_cast<float4*>(&bb[0]) = *reinterpret_cast<const float4*>(&Bs[k][tx*8+0]);
            *reinterpret_cast<float4*>(&bb[4]) = *reinterpret_cast<const float4*>(&Bs[k][tx*8+4]);
            #pragma unroll
            for (int i = 0; i < 8; i++)
                #pragma unroll
                for (int j = 0; j < 8; j++)
                    acc[i][j] = fmaf(a[i], bb[j], acc[i][j]);
        }
        __syncthreads();
    }

    // ---- epilogue ----
    #pragma unroll
    for (int i = 0; i < 8; i++) {
        int row = bm + ty*8 + i;
        #pragma unroll
        for (int j = 0; j < 8; j++) {
            int col = bn + tx*8 + j;
            if (col < N) {
                float v = acc[i][j];
                if (EP == 1) {
                    float g = E[(size_t)row*lde + eoff + col];
                    v *= g / (1.f + __expf(-g));     // silu(gate)
                } else if (EP == 2) {
                    v += E[(size_t)row*lde + col];   // residual
                }
                C[(size_t)row*N + col] = v;
            }
        }
    }
}

// ===================== depthwise causal conv (K=4) + SiLU =====================
__global__ __launch_bounds__(256) void conv_silu_k(
    const float* __restrict__ xp, const float* __restrict__ cw,
    float* __restrict__ u)
{
    int idx = blockIdx.x*blockDim.x + threadIdx.x;
    if (idx >= TOK*INNER) return;
    int c = idx % INNER;
    int t = idx / INNER;
    int s = t & (SEQ-1);
    const float* base = xp + (size_t)t*XPW + c;   // u-half of xp
    float w0 = cw[c*4+0], w1 = cw[c*4+1], w2 = cw[c*4+2], w3 = cw[c*4+3];
    float acc = w3 * base[0];
    if (s >= 1) acc = fmaf(w2, base[-(size_t)XPW],   acc);
    if (s >= 2) acc = fmaf(w1, base[-(size_t)2*XPW], acc);
    if (s >= 3) acc = fmaf(w0, base[-(size_t)3*XPW], acc);
    u[idx] = acc / (1.f + __expf(-acc));          // silu
}

// ===================== selective scan =====================
// one warp per 32 channels per batch; h[16] in registers; B/C broadcast via smem
__global__ __launch_bounds__(32) void scan_kernel(
    const float* __restrict__ proj, const float* __restrict__ u,
    const float* __restrict__ A_log, const float* __restrict__ D,
    float* __restrict__ y)
{
    const int lane = threadIdx.x;              // 0..31
    const int blk  = blockIdx.x;               // 0..95
    const int b    = blk / (INNER/32);
    const int c    = (blk % (INNER/32))*32 + lane;
    __shared__ float sBC[32];                  // [0:16)=B, [16:32)=C

    float A[NSTATE];
    #pragma unroll
    for (int n = 0; n < NSTATE; n++) A[n] = -__expf(A_log[n]);
    float h[NSTATE];
    #pragma unroll
    for (int n = 0; n < NSTATE; n++) h[n] = 0.f;
    const float Dv = D[c];

    size_t rowP = (size_t)b*SEQ*PJW;
    size_t rowU = (size_t)b*SEQ*INNER;
    for (int s = 0; s < SEQ; s++) {
        sBC[lane] = proj[rowP + lane];
        __syncwarp();
        float p  = proj[rowP + 2*NSTATE + c];
        float uu = u[rowU + c];
        float delta = (p > 20.f) ? p : log1pf(__expf(p));   // softplus
        float du = delta * uu;
        float yv = Dv * uu;
        #pragma unroll
        for (int n = 0; n < NSTATE; n++) {
            float dA = __expf(delta * A[n]);
            h[n] = fmaf(dA, h[n], du * sBC[n]);
            yv   = fmaf(h[n], sBC[16+n], yv);
        }
        y[rowU + c] = yv;
        __syncwarp();
        rowP += PJW; rowU += INNER;
    }
}

// ===================== launch =====================
extern "C" void kernel_launch(void* const* d_in, const int* in_sizes, int n_in,
                              void* d_out, int out_size)
{
    const float* x      = (const float*)d_in[0];
    const float* norm_w = (const float*)d_in[1];
    const float* norm_b = (const float*)d_in[2];
    const float* W_in   = (const float*)d_in[3];
    const float* conv_w = (const float*)d_in[4];
    const float* W_xprj = (const float*)d_in[5];
    const float* A_log  = (const float*)d_in[6];
    const float* D      = (const float*)d_in[7];
    const float* W_ssm  = (const float*)d_in[8];
    const float* W_out  = (const float*)d_in[9];
    float* out = (float*)d_out;

    void *p_xn, *p_xp, *p_u, *p_pj, *p_y1, *p_y2;
    cudaGetSymbolAddress(&p_xn, g_xn);
    cudaGetSymbolAddress(&p_xp, g_xp);
    cudaGetSymbolAddress(&p_u,  g_u);
    cudaGetSymbolAddress(&p_pj, g_pj);
    cudaGetSymbolAddress(&p_y1, g_y1);
    cudaGetSymbolAddress(&p_y2, g_y2);
    float* xn = (float*)p_xn; float* xp = (float*)p_xp;
    float* u  = (float*)p_u;  float* pj = (float*)p_pj;
    float* y1 = (float*)p_y1; float* y2 = (float*)p_y2;

    // 1. LayerNorm
    ln_kernel<<<TOK, 256>>>(x, norm_w, norm_b, xn);

    // 2. xp = xn @ W_in   (4096x768 @ 768x3072)
    sgemm_k<0><<<dim3(XPW/128, TOK/128), 256>>>(xn, W_in, xp, TOK, XPW, HID,
                                                nullptr, 0, 0);

    // 3. depthwise conv + silu -> u
    conv_silu_k<<<(TOK*INNER + 255)/256, 256>>>(xp, conv_w, u);

    // 4. proj = u @ W_xproj  (4096x1536 @ 1536x1568)
    sgemm_k<0><<<dim3((PJW + 127)/128, TOK/128), 256>>>(u, W_xprj, pj, TOK, PJW, INNER,
                                                        nullptr, 0, 0);

    // 5. selective scan -> y1 (includes +D*u)
    scan_kernel<<<BATCH*(INNER/32), 32>>>(pj, u, A_log, D, y1);

    // 6. y2 = (y1 @ W_ssm_out) * silu(gate)   gate = xp[:, 1536:]
    sgemm_k<1><<<dim3(INNER/128, TOK/128), 256>>>(y1, W_ssm, y2, TOK, INNER, INNER,
                                                  xp, XPW, INNER);

    // 7. out = y2 @ W_out + x
    sgemm_k<2><<<dim3(HID/128, TOK/128), 256>>>(y2, W_out, out, TOK, HID, INNER,
                                                x, HID, 0);
}

// round 7
// speedup vs baseline: 2.0738x; 2.0738x over previous
#include <cuda_runtime.h>
#include <cuda_bf16.h>
#include <cstdint>
#include <math.h>

#define BATCH 2
#define SEQ   2048
#define TOK   (BATCH*SEQ)        // 4096
#define HID   768
#define INNER 1536
#define NSTATE 16
#define XPW   (2*INNER)          // 3072
#define PJW   (2*NSTATE+INNER)   // 1568
#define NPADX 1664               // PJW padded to multiple of 128

// ---------------- scratch (device globals; allocation-free) ----------------
__device__ __nv_bfloat16 g_xnh[TOK*HID], g_xnl[TOK*HID];
__device__ float         g_xp [TOK*XPW];
__device__ float         g_u  [TOK*INNER];
__device__ __nv_bfloat16 g_uh [TOK*INNER], g_ul [TOK*INNER];
__device__ float         g_pj [TOK*PJW];
__device__ __nv_bfloat16 g_y1h[TOK*INNER], g_y1l[TOK*INNER];
__device__ __nv_bfloat16 g_y2h[TOK*INNER], g_y2l[TOK*INNER];
// transposed + split weights: [Npad rows, K cols] bf16
__device__ __nv_bfloat16 g_Wih[XPW*HID],     g_Wil[XPW*HID];
__device__ __nv_bfloat16 g_Wxh[NPADX*INNER], g_Wxl[NPADX*INNER];
__device__ __nv_bfloat16 g_Wsh[INNER*INNER], g_Wsl[INNER*INNER];
__device__ __nv_bfloat16 g_Woh[HID*INNER],   g_Wol[HID*INNER];

// ---------------- helpers ----------------
__device__ __forceinline__ uint32_t smaddr(const void* p){
    uint32_t r;
    asm("{ .reg .u64 t; cvta.to.shared.u64 t, %1; cvt.u32.u64 %0, t; }"
        : "=r"(r) : "l"(p));
    return r;
}
__device__ __forceinline__ void cp16(uint32_t s, const void* g){
    asm volatile("cp.async.cg.shared.global [%0], [%1], 16;" :: "r"(s), "l"(g));
}
__device__ __forceinline__ void ldm4(uint32_t& r0, uint32_t& r1,
                                     uint32_t& r2, uint32_t& r3, uint32_t a){
    asm volatile("ldmatrix.sync.aligned.m8n8.x4.shared.b16 {%0,%1,%2,%3}, [%4];"
                 : "=r"(r0), "=r"(r1), "=r"(r2), "=r"(r3) : "r"(a));
}
__device__ __forceinline__ void mma16816(float* d, const uint32_t* a,
                                         const uint32_t* b){
    asm volatile("mma.sync.aligned.m16n8k16.row.col.f32.bf16.bf16.f32 "
                 "{%0,%1,%2,%3}, {%4,%5,%6,%7}, {%8,%9}, {%0,%1,%2,%3};"
                 : "+f"(d[0]), "+f"(d[1]), "+f"(d[2]), "+f"(d[3])
                 : "r"(a[0]), "r"(a[1]), "r"(a[2]), "r"(a[3]),
                   "r"(b[0]), "r"(b[1]));
}

// ---------------- weight transpose + split:  W[K,N] -> Th/Tl[Npad,K] ----------------
__global__ __launch_bounds__(256) void tsplit_k(
    const float* __restrict__ W, int K, int N, int Npad,
    __nv_bfloat16* __restrict__ Th, __nv_bfloat16* __restrict__ Tl)
{
    __shared__ float t[32][33];
    int k0 = blockIdx.y*32, n0 = blockIdx.x*32;
    int tx = threadIdx.x, ty = threadIdx.y;   // (32,8)
    #pragma unroll
    for (int i = 0; i < 32; i += 8) {
        int k = k0 + ty + i;
        float v = (n0 + tx < N) ? W[(size_t)k*N + n0 + tx] : 0.f;
        t[ty+i][tx] = v;
    }
    __syncthreads();
    #pragma unroll
    for (int i = 0; i < 32; i += 8) {
        int n = n0 + ty + i;
        float v = t[tx][ty+i];
        __nv_bfloat16 h = __float2bfloat16(v);
        Th[(size_t)n*K + k0 + tx] = h;
        Tl[(size_t)n*K + k0 + tx] = __float2bfloat16(v - __bfloat162float(h));
    }
}

// ---------------- LayerNorm -> bf16 hi/lo splits ----------------
__global__ __launch_bounds__(256) void ln_kernel(
    const float* __restrict__ x, const float* __restrict__ w,
    const float* __restrict__ b,
    __nv_bfloat16* __restrict__ oh, __nv_bfloat16* __restrict__ ol)
{
    int t = blockIdx.x;
    const float* xr = x + (size_t)t*HID;
    float s = 0.f, s2 = 0.f;
    for (int i = threadIdx.x; i < HID; i += 256) {
        float v = xr[i]; s += v; s2 += v*v;
    }
    __shared__ float r0[32], r1[32];
    #pragma unroll
    for (int off = 16; off > 0; off >>= 1) {
        s  += __shfl_down_sync(0xffffffffu, s,  off);
        s2 += __shfl_down_sync(0xffffffffu, s2, off);
    }
    int wid = threadIdx.x >> 5, lid = threadIdx.x & 31;
    if (lid == 0) { r0[wid] = s; r1[wid] = s2; }
    __syncthreads();
    if (wid == 0) {
        s  = (lid < 8) ? r0[lid] : 0.f;
        s2 = (lid < 8) ? r1[lid] : 0.f;
        #pragma unroll
        for (int off = 4; off > 0; off >>= 1) {
            s  += __shfl_down_sync(0xffffffffu, s,  off);
            s2 += __shfl_down_sync(0xffffffffu, s2, off);
        }
        if (lid == 0) { r0[0] = s; r1[0] = s2; }
    }
    __syncthreads();
    float mu  = r0[0] * (1.f/HID);
    float var = r1[0] * (1.f/HID) - mu*mu;
    float inv = rsqrtf(var + 1e-5f);
    for (int i = threadIdx.x; i < HID; i += 256) {
        float v = (xr[i] - mu) * inv * w[i] + b[i];
        __nv_bfloat16 h = __float2bfloat16(v);
        oh[(size_t)t*HID + i] = h;
        ol[(size_t)t*HID + i] = __float2bfloat16(v - __bfloat162float(h));
    }
}

// ---------------- split-bf16 HMMA GEMM ----------------
// C[M,N] = A @ B^T with B pre-transposed [Npad, K] bf16 splits.
// Exact-ish fp32: Ah*Bh + Ah*Bl + Al*Bh via 3 K-segments in one mainloop.
// CTA 128x128, K-chunk 64, 8 warps (warp tile 64x32), cp.async double buffer.
// EP=0: store fp32 C; EP=1: v*=silu(E[..eoff+col]) -> bf16 splits; EP=2: v+=E -> fp32.
template<int EP>
__global__ __launch_bounds__(256) void hgemm(
    const __nv_bfloat16* __restrict__ Ah, const __nv_bfloat16* __restrict__ Al,
    const __nv_bfloat16* __restrict__ Bh, const __nv_bfloat16* __restrict__ Bl,
    float* __restrict__ C, int M, int N, int K, int ldc,
    const float* __restrict__ E, int lde, int eoff,
    __nv_bfloat16* __restrict__ Ch, __nv_bfloat16* __restrict__ Cl)
{
    extern __shared__ __align__(16) char dsm[];
    const int tid  = threadIdx.x;
    const int wid  = tid >> 5, lane = tid & 31;
    const int wm   = wid >> 2, wn = wid & 3;      // 2 x 4 warps
    const int bm   = blockIdx.y*128, bn = blockIdx.x*128;

    uint32_t dyn  = smaddr(dsm);
    uint32_t base = (dyn + 1023u) & ~1023u;       // 1024B-align for swizzle

    const int KCH = K >> 6;                        // chunks per segment
    const int NC  = 3*KCH;

    float acc[4][4][4];
    #pragma unroll
    for (int i = 0; i < 4; i++)
        #pragma unroll
        for (int j = 0; j < 4; j++)
            #pragma unroll
            for (int r = 0; r < 4; r++) acc[i][j][r] = 0.f;

    auto load_stage = [&](int st, int c){
        int seg = c / KCH;
        int kk  = (c - seg*KCH) << 6;
        const __nv_bfloat16* Ap = (seg < 2) ? Ah : Al;
        const __nv_bfloat16* Bp = (seg == 1) ? Bl : Bh;
        uint32_t sA = base + st*32768;
        uint32_t sB = sA + 16384;
        #pragma unroll
        for (int i = 0; i < 4; i++) {
            int q  = i*256 + tid;
            int r  = q >> 3, c16 = q & 7;
            uint32_t off = (uint32_t)(r*128 + c16*16);
            off ^= ((off >> 3) & 0x70);
            cp16(sA + off, Ap + (size_t)(bm + r)*K + kk + c16*8);
            cp16(sB + off, Bp + (size_t)(bn + r)*K + kk + c16*8);
        }
    };

    auto compute = [&](int st){
        uint32_t sA = base + st*32768;
        uint32_t sB = sA + 16384;
        #pragma unroll
        for (int ks = 0; ks < 4; ks++) {
            uint32_t a[4][4], b[4][2];
            #pragma unroll
            for (int mt = 0; mt < 4; mt++) {
                uint32_t row = wm*64 + mt*16 + (lane & 15);
                uint32_t off = row*128 + ks*32 + ((lane >> 4) & 1)*16;
                off ^= ((off >> 3) & 0x70);
                ldm4(a[mt][0], a[mt][1], a[mt][2], a[mt][3], sA + off);
            }
            #pragma unroll
            for (int nh = 0; nh < 2; nh++) {
                uint32_t row = wn*32 + nh*16 + (lane & 7) + ((lane >> 4) & 1)*8;
                uint32_t off = row*128 + ks*32 + ((lane >> 3) & 1)*16;
                off ^= ((off >> 3) & 0x70);
                ldm4(b[nh*2][0], b[nh*2][1], b[nh*2+1][0], b[nh*2+1][1], sB + off);
            }
            #pragma unroll
            for (int mt = 0; mt < 4; mt++)
                #pragma unroll
                for (int nt = 0; nt < 4; nt++)
                    mma16816(acc[mt][nt], a[mt], b[nt]);
        }
    };

    load_stage(0, 0);
    asm volatile("cp.async.commit_group;");
    for (int c = 0; c < NC; c++) {
        if (c + 1 < NC) {
            load_stage((c+1) & 1, c+1);
            asm volatile("cp.async.commit_group;");
            asm volatile("cp.async.wait_group 1;");
        } else {
            asm volatile("cp.async.wait_group 0;");
        }
        __syncthreads();
        compute(c & 1);
        __syncthreads();
    }

    // ---- epilogue ----
    #pragma unroll
    for (int mt = 0; mt < 4; mt++) {
        #pragma unroll
        for (int half = 0; half < 2; half++) {
            int row = bm + wm*64 + mt*16 + (lane >> 2) + half*8;
            #pragma unroll
            for (int nt = 0; nt < 4; nt++) {
                int col = bn + wn*32 + nt*8 + (lane & 3)*2;
                if (col < N) {
                    float v0 = acc[mt][nt][half*2 + 0];
                    float v1 = acc[mt][nt][half*2 + 1];
                    if constexpr (EP == 1) {
                        float g0 = E[(size_t)row*lde + eoff + col];
                        float g1 = E[(size_t)row*lde + eoff + col + 1];
                        v0 *= g0 / (1.f + __expf(-g0));
                        v1 *= g1 / (1.f + __expf(-g1));
                        __nv_bfloat16 h0 = __float2bfloat16(v0);
                        __nv_bfloat16 h1 = __float2bfloat16(v1);
                        Ch[(size_t)row*ldc + col]   = h0;
                        Ch[(size_t)row*ldc + col+1] = h1;
                        Cl[(size_t)row*ldc + col]   = __float2bfloat16(v0 - __bfloat162float(h0));
                        Cl[(size_t)row*ldc + col+1] = __float2bfloat16(v1 - __bfloat162float(h1));
                    } else {
                        if constexpr (EP == 2) {
                            v0 += E[(size_t)row*lde + col];
                            v1 += E[(size_t)row*lde + col + 1];
                        }
                        *reinterpret_cast<float2*>(C + (size_t)row*ldc + col) =
                            make_float2(v0, v1);
                    }
                }
            }
        }
    }
}

// ---------------- depthwise causal conv (K=4) + SiLU -> fp32 + splits ----------------
__global__ __launch_bounds__(256) void conv_silu_k(
    const float* __restrict__ xp, const float* __restrict__ cw,
    float* __restrict__ u, __nv_bfloat16* __restrict__ uh, __nv_bfloat16* __restrict__ ul)
{
    int idx = blockIdx.x*blockDim.x + threadIdx.x;
    if (idx >= TOK*INNER) return;
    int c = idx % INNER;
    int t = idx / INNER;
    int s = t & (SEQ-1);
    const float* bp = xp + (size_t)t*XPW + c;
    float w0 = cw[c*4+0], w1 = cw[c*4+1], w2 = cw[c*4+2], w3 = cw[c*4+3];
    float acc = w3 * bp[0];
    if (s >= 1) acc = fmaf(w2, bp[-(ptrdiff_t)XPW],     acc);
    if (s >= 2) acc = fmaf(w1, bp[-(ptrdiff_t)(2*XPW)], acc);
    if (s >= 3) acc = fmaf(w0, bp[-(ptrdiff_t)(3*XPW)], acc);
    float v = acc / (1.f + __expf(-acc));
    u[idx] = v;
    __nv_bfloat16 h = __float2bfloat16(v);
    uh[idx] = h;
    ul[idx] = __float2bfloat16(v - __bfloat162float(h));
}

// ---------------- selective scan: thread per (channel,state) ----------------
__global__ __launch_bounds__(512) void scan_kernel(
    const float* __restrict__ proj, const float* __restrict__ u,
    const float* __restrict__ A_log, const float* __restrict__ D,
    __nv_bfloat16* __restrict__ yh, __nv_bfloat16* __restrict__ yl)
{
    const int tid = threadIdx.x;
    const int n   = tid & 15;
    const int cl  = tid >> 4;                 // 0..31
    const int blk = blockIdx.x;               // 0..95
    const int b   = blk / 48;
    const int c   = (blk % 48)*32 + cl;
    const float a  = -__expf(A_log[n]);
    const float Dv = D[c];
    float h = 0.f;
    size_t rowP = (size_t)b*SEQ*PJW;
    size_t rowU = (size_t)b*SEQ*INNER;
    float pB = proj[rowP + n];
    float pC = proj[rowP + 16 + n];
    float pp = proj[rowP + 32 + c];
    float pu = u[rowU + c];
    for (int s = 0; s < SEQ; s++) {
        float B_ = pB, C_ = pC, p = pp, uu = pu;
        if (s + 1 < SEQ) {
            size_t nP = rowP + PJW, nU = rowU + INNER;
            pB = proj[nP + n];
            pC = proj[nP + 16 + n];
            pp = proj[nP + 32 + c];
            pu = u[nU + c];
        }
        float delta = (p > 20.f) ? p : __logf(1.f + __expf(p));
        float dA = __expf(delta * a);
        h = fmaf(dA, h, delta * uu * B_);
        float yv = h * C_;
        yv += __shfl_down_sync(0xffffffffu, yv, 8, 16);
        yv += __shfl_down_sync(0xffffffffu, yv, 4, 16);
        yv += __shfl_down_sync(0xffffffffu, yv, 2, 16);
        yv += __shfl_down_sync(0xffffffffu, yv, 1, 16);
        if (n == 0) {
            float outv = yv + Dv * uu;
            __nv_bfloat16 hh = __float2bfloat16(outv);
            yh[rowU + c] = hh;
            yl[rowU + c] = __float2bfloat16(outv - __bfloat162float(hh));
        }
        rowP += PJW; rowU += INNER;
    }
}

// ---------------- launch ----------------
extern "C" void kernel_launch(void* const* d_in, const int* in_sizes, int n_in,
                              void* d_out, int out_size)
{
    const float* x      = (const float*)d_in[0];
    const float* norm_w = (const float*)d_in[1];
    const float* norm_b = (const float*)d_in[2];
    const float* W_in   = (const float*)d_in[3];
    const float* conv_w = (const float*)d_in[4];
    const float* W_xprj = (const float*)d_in[5];
    const float* A_log  = (const float*)d_in[6];
    const float* D      = (const float*)d_in[7];
    const float* W_ssm  = (const float*)d_in[8];
    const float* W_out  = (const float*)d_in[9];
    float* out = (float*)d_out;

    #define SYM(v, g) void* p_##v; cudaGetSymbolAddress(&p_##v, g);
    SYM(xnh, g_xnh) SYM(xnl, g_xnl) SYM(xp, g_xp) SYM(u, g_u)
    SYM(uh, g_uh)   SYM(ul, g_ul)   SYM(pj, g_pj)
    SYM(y1h, g_y1h) SYM(y1l, g_y1l) SYM(y2h, g_y2h) SYM(y2l, g_y2l)
    SYM(Wih, g_Wih) SYM(Wil, g_Wil) SYM(Wxh, g_Wxh) SYM(Wxl, g_Wxl)
    SYM(Wsh, g_Wsh) SYM(Wsl, g_Wsl) SYM(Woh, g_Woh) SYM(Wol, g_Wol)
    #undef SYM
    typedef __nv_bfloat16 bf;

    const int SMEM = 2*32768 + 1024;
    cudaFuncSetAttribute(hgemm<0>, cudaFuncAttributeMaxDynamicSharedMemorySize, SMEM);
    cudaFuncSetAttribute(hgemm<1>, cudaFuncAttributeMaxDynamicSharedMemorySize, SMEM);
    cudaFuncSetAttribute(hgemm<2>, cudaFuncAttributeMaxDynamicSharedMemorySize, SMEM);

    dim3 tb(32, 8);
    tsplit_k<<<dim3(XPW/32,  HID/32),   tb>>>(W_in,   HID,   XPW,  XPW,  (bf*)p_Wih, (bf*)p_Wil);
    tsplit_k<<<dim3(NPADX/32,INNER/32), tb>>>(W_xprj, INNER, PJW,  NPADX,(bf*)p_Wxh, (bf*)p_Wxl);
    tsplit_k<<<dim3(INNER/32,INNER/32), tb>>>(W_ssm,  INNER, INNER,INNER,(bf*)p_Wsh, (bf*)p_Wsl);
    tsplit_k<<<dim3(HID/32,  INNER/32), tb>>>(W_out,  INNER, HID,  HID,  (bf*)p_Woh, (bf*)p_Wol);

    // 1. LayerNorm -> splits
    ln_kernel<<<TOK, 256>>>(x, norm_w, norm_b, (bf*)p_xnh, (bf*)p_xnl);

    // 2. xp = xn @ W_in  (4096 x 3072 x 768)
    hgemm<0><<<dim3(XPW/128, TOK/128), 256, SMEM>>>(
        (bf*)p_xnh, (bf*)p_xnl, (bf*)p_Wih, (bf*)p_Wil,
        (float*)p_xp, TOK, XPW, HID, XPW, nullptr, 0, 0, nullptr, nullptr);

    // 3. conv + silu -> u (fp32 + splits)
    conv_silu_k<<<(TOK*INNER + 255)/256, 256>>>(
        (float*)p_xp, conv_w, (float*)p_u, (bf*)p_uh, (bf*)p_ul);

    // 4. proj = u @ W_xproj  (4096 x 1568 x 1536)
    hgemm<0><<<dim3(NPADX/128, TOK/128), 256, SMEM>>>(
        (bf*)p_uh, (bf*)p_ul, (bf*)p_Wxh, (bf*)p_Wxl,
        (float*)p_pj, TOK, PJW, INNER, PJW, nullptr, 0, 0, nullptr, nullptr);

    // 5. selective scan -> y1 splits (includes +D*u)
    scan_kernel<<<96, 512>>>((float*)p_pj, (float*)p_u, A_log, D,
                             (bf*)p_y1h, (bf*)p_y1l);

    // 6. y2 = (y1 @ W_ssm_out) * silu(gate) -> splits
    hgemm<1><<<dim3(INNER/128, TOK/128), 256, SMEM>>>(
        (bf*)p_y1h, (bf*)p_y1l, (bf*)p_Wsh, (bf*)p_Wsl,
        nullptr, TOK, INNER, INNER, INNER,
        (float*)p_xp, XPW, INNER, (bf*)p_y2h, (bf*)p_y2l);

    // 7. out = y2 @ W_out + x
    hgemm<2><<<dim3(HID/128, TOK/128), 256, SMEM>>>(
        (bf*)p_y2h, (bf*)p_y2l, (bf*)p_Woh, (bf*)p_Wol,
        out, TOK, HID, INNER, HID, x, HID, 0, nullptr, nullptr);
}

// round 11
// speedup vs baseline: 3.1385x; 1.5134x over previous
#include <cuda_runtime.h>
#include <cuda_bf16.h>
#include <cstdint>
#include <math.h>

#define BATCH 2
#define SEQ   2048
#define TOK   (BATCH*SEQ)        // 4096
#define HID   768
#define INNER 1536
#define NSTATE 16
#define XPW   (2*INNER)          // 3072
#define PJW   (2*NSTATE+INNER)   // 1568
#define NPADX 1664               // PJW padded to multiple of 128

// ---------------- scratch (device globals; allocation-free) ----------------
__device__ __nv_bfloat16 g_xnh[TOK*HID], g_xnl[TOK*HID];
__device__ float         g_xp [TOK*XPW];
__device__ float         g_u  [TOK*INNER];
__device__ __nv_bfloat16 g_uh [TOK*INNER], g_ul [TOK*INNER];
__device__ float         g_pj [TOK*PJW];
__device__ __nv_bfloat16 g_y1h[TOK*INNER], g_y1l[TOK*INNER];
__device__ __nv_bfloat16 g_y2h[TOK*INNER], g_y2l[TOK*INNER];
// transposed + split weights: [Npad rows, K cols] bf16
__device__ __nv_bfloat16 g_Wih[XPW*HID],     g_Wil[XPW*HID];
__device__ __nv_bfloat16 g_Wxh[NPADX*INNER], g_Wxl[NPADX*INNER];
__device__ __nv_bfloat16 g_Wsh[INNER*INNER], g_Wsl[INNER*INNER];
__device__ __nv_bfloat16 g_Woh[HID*INNER],   g_Wol[HID*INNER];

// ---------------- helpers ----------------
__device__ __forceinline__ uint32_t smaddr(const void* p){
    uint32_t r;
    asm("{ .reg .u64 t; cvta.to.shared.u64 t, %1; cvt.u32.u64 %0, t; }"
        : "=r"(r) : "l"(p));
    return r;
}
__device__ __forceinline__ void cp16(uint32_t s, const void* g){
    asm volatile("cp.async.cg.shared.global [%0], [%1], 16;" :: "r"(s), "l"(g));
}
__device__ __forceinline__ void ldm4(uint32_t& r0, uint32_t& r1,
                                     uint32_t& r2, uint32_t& r3, uint32_t a){
    asm volatile("ldmatrix.sync.aligned.m8n8.x4.shared.b16 {%0,%1,%2,%3}, [%4];"
                 : "=r"(r0), "=r"(r1), "=r"(r2), "=r"(r3) : "r"(a));
}
__device__ __forceinline__ void mma16816(float* d, const uint32_t* a,
                                         const uint32_t* b){
    asm volatile("mma.sync.aligned.m16n8k16.row.col.f32.bf16.bf16.f32 "
                 "{%0,%1,%2,%3}, {%4,%5,%6,%7}, {%8,%9}, {%0,%1,%2,%3};"
                 : "+f"(d[0]), "+f"(d[1]), "+f"(d[2]), "+f"(d[3])
                 : "r"(a[0]), "r"(a[1]), "r"(a[2]), "r"(a[3]),
                   "r"(b[0]), "r"(b[1]));
}

// ---------------- weight transpose + split:  W[K,N] -> Th/Tl[Npad,K] ----------------
__global__ __launch_bounds__(256) void tsplit_k(
    const float* __restrict__ W, int K, int N, int Npad,
    __nv_bfloat16* __restrict__ Th, __nv_bfloat16* __restrict__ Tl)
{
    __shared__ float t[32][33];
    int k0 = blockIdx.y*32, n0 = blockIdx.x*32;
    int tx = threadIdx.x, ty = threadIdx.y;   // (32,8)
    #pragma unroll
    for (int i = 0; i < 32; i += 8) {
        int k = k0 + ty + i;
        float v = (n0 + tx < N) ? W[(size_t)k*N + n0 + tx] : 0.f;
        t[ty+i][tx] = v;
    }
    __syncthreads();
    #pragma unroll
    for (int i = 0; i < 32; i += 8) {
        int n = n0 + ty + i;
        float v = t[tx][ty+i];
        __nv_bfloat16 h = __float2bfloat16(v);
        Th[(size_t)n*K + k0 + tx] = h;
        Tl[(size_t)n*K + k0 + tx] = __float2bfloat16(v - __bfloat162float(h));
    }
}

// ---------------- LayerNorm -> bf16 hi/lo splits ----------------
__global__ __launch_bounds__(256) void ln_kernel(
    const float* __restrict__ x, const float* __restrict__ w,
    const float* __restrict__ b,
    __nv_bfloat16* __restrict__ oh, __nv_bfloat16* __restrict__ ol)
{
    int t = blockIdx.x;
    const float* xr = x + (size_t)t*HID;
    float s = 0.f, s2 = 0.f;
    for (int i = threadIdx.x; i < HID; i += 256) {
        float v = xr[i]; s += v; s2 += v*v;
    }
    __shared__ float r0[32], r1[32];
    #pragma unroll
    for (int off = 16; off > 0; off >>= 1) {
        s  += __shfl_down_sync(0xffffffffu, s,  off);
        s2 += __shfl_down_sync(0xffffffffu, s2, off);
    }
    int wid = threadIdx.x >> 5, lid = threadIdx.x & 31;
    if (lid == 0) { r0[wid] = s; r1[wid] = s2; }
    __syncthreads();
    if (wid == 0) {
        s  = (lid < 8) ? r0[lid] : 0.f;
        s2 = (lid < 8) ? r1[lid] : 0.f;
        #pragma unroll
        for (int off = 4; off > 0; off >>= 1) {
            s  += __shfl_down_sync(0xffffffffu, s,  off);
            s2 += __shfl_down_sync(0xffffffffu, s2, off);
        }
        if (lid == 0) { r0[0] = s; r1[0] = s2; }
    }
    __syncthreads();
    float mu  = r0[0] * (1.f/HID);
    float var = r1[0] * (1.f/HID) - mu*mu;
    float inv = rsqrtf(var + 1e-5f);
    for (int i = threadIdx.x; i < HID; i += 256) {
        float v = (xr[i] - mu) * inv * w[i] + b[i];
        __nv_bfloat16 h = __float2bfloat16(v);
        oh[(size_t)t*HID + i] = h;
        ol[(size_t)t*HID + i] = __float2bfloat16(v - __bfloat162float(h));
    }
}

// ---------------- split-bf16 HMMA GEMM ----------------
// C[M,N] = A @ B^T (B pre-transposed [Npad,K]); Ah*Bh + Ah*Bl + Al*Bh via
// 3 K-segments in one mainloop. CTA 128x128, K-chunk 64, 8 warps, 3-stage
// cp.async pipeline, ONE __syncthreads per chunk, 2 CTAs/SM.
template<int EP>
__global__ __launch_bounds__(256, 2) void hgemm(
    const __nv_bfloat16* __restrict__ Ah, const __nv_bfloat16* __restrict__ Al,
    const __nv_bfloat16* __restrict__ Bh, const __nv_bfloat16* __restrict__ Bl,
    float* __restrict__ C, int M, int N, int K, int ldc,
    const float* __restrict__ E, int lde, int eoff,
    __nv_bfloat16* __restrict__ Ch, __nv_bfloat16* __restrict__ Cl)
{
    extern __shared__ __align__(16) char dsm[];
    const int tid  = threadIdx.x;
    const int wid  = tid >> 5, lane = tid & 31;
    const int wm   = wid >> 2, wn = wid & 3;      // 2 x 4 warps
    const int bm   = blockIdx.y*128, bn = blockIdx.x*128;

    uint32_t dyn  = smaddr(dsm);
    uint32_t base = (dyn + 1023u) & ~1023u;       // 1024B-align for swizzle

    const int KCH = K >> 6;                        // chunks per segment
    const int NC  = 3*KCH;

    float acc[4][4][4];
    #pragma unroll
    for (int i = 0; i < 4; i++)
        #pragma unroll
        for (int j = 0; j < 4; j++)
            #pragma unroll
            for (int r = 0; r < 4; r++) acc[i][j][r] = 0.f;

    auto load_stage = [&](int st, int c){
        int seg = c / KCH;
        int kk  = (c - seg*KCH) << 6;
        const __nv_bfloat16* Ap = (seg < 2) ? Ah : Al;
        const __nv_bfloat16* Bp = (seg == 1) ? Bl : Bh;
        uint32_t sA = base + st*32768;
        uint32_t sB = sA + 16384;
        #pragma unroll
        for (int i = 0; i < 4; i++) {
            int q  = i*256 + tid;
            int r  = q >> 3, c16 = q & 7;
            uint32_t off = (uint32_t)(r*128 + c16*16);
            off ^= ((off >> 3) & 0x70);
            cp16(sA + off, Ap + (size_t)(bm + r)*K + kk + c16*8);
            cp16(sB + off, Bp + (size_t)(bn + r)*K + kk + c16*8);
        }
    };

    auto compute = [&](int st){
        uint32_t sA = base + st*32768;
        uint32_t sB = sA + 16384;
        #pragma unroll
        for (int ks = 0; ks < 4; ks++) {
            uint32_t a[4][4], b[4][2];
            #pragma unroll
            for (int mt = 0; mt < 4; mt++) {
                uint32_t row = wm*64 + mt*16 + (lane & 15);
                uint32_t off = row*128 + ks*32 + ((lane >> 4) & 1)*16;
                off ^= ((off >> 3) & 0x70);
                ldm4(a[mt][0], a[mt][1], a[mt][2], a[mt][3], sA + off);
            }
            #pragma unroll
            for (int nh = 0; nh < 2; nh++) {
                uint32_t row = wn*32 + nh*16 + (lane & 7) + ((lane >> 4) & 1)*8;
                uint32_t off = row*128 + ks*32 + ((lane >> 3) & 1)*16;
                off ^= ((off >> 3) & 0x70);
                ldm4(b[nh*2][0], b[nh*2][1], b[nh*2+1][0], b[nh*2+1][1], sB + off);
            }
            #pragma unroll
            for (int mt = 0; mt < 4; mt++)
                #pragma unroll
                for (int nt = 0; nt < 4; nt++)
                    mma16816(acc[mt][nt], a[mt], b[nt]);
        }
    };

    // 3-stage pipeline: stage (c+2)%3 is reloaded right after the sync at
    // iter c (it was consumed at iter c-1; the sync proves all warps passed).
    load_stage(0, 0);
    asm volatile("cp.async.commit_group;");
    load_stage(1, 1);
    asm volatile("cp.async.commit_group;");
    int st = 0, ld = 2;
    for (int c = 0; c < NC; c++) {
        asm volatile("cp.async.wait_group 1;");
        __syncthreads();
        if (c + 2 < NC) load_stage(ld, c + 2);
        asm volatile("cp.async.commit_group;");
        compute(st);
        st = (st == 2) ? 0 : st + 1;
        ld = (ld == 2) ? 0 : ld + 1;
    }

    // ---- epilogue ----
    #pragma unroll
    for (int mt = 0; mt < 4; mt++) {
        #pragma unroll
        for (int half = 0; half < 2; half++) {
            int row = bm + wm*64 + mt*16 + (lane >> 2) + half*8;
            #pragma unroll
            for (int nt = 0; nt < 4; nt++) {
                int col = bn + wn*32 + nt*8 + (lane & 3)*2;
                if (col < N) {
                    float v0 = acc[mt][nt][half*2 + 0];
                    float v1 = acc[mt][nt][half*2 + 1];
                    if constexpr (EP == 1) {
                        float g0 = E[(size_t)row*lde + eoff + col];
                        float g1 = E[(size_t)row*lde + eoff + col + 1];
                        v0 *= g0 / (1.f + __expf(-g0));
                        v1 *= g1 / (1.f + __expf(-g1));
                        __nv_bfloat16 h0 = __float2bfloat16(v0);
                        __nv_bfloat16 h1 = __float2bfloat16(v1);
                        Ch[(size_t)row*ldc + col]   = h0;
                        Ch[(size_t)row*ldc + col+1] = h1;
                        Cl[(size_t)row*ldc + col]   = __float2bfloat16(v0 - __bfloat162float(h0));
                        Cl[(size_t)row*ldc + col+1] = __float2bfloat16(v1 - __bfloat162float(h1));
                    } else {
                        if constexpr (EP == 2) {
                            v0 += E[(size_t)row*lde + col];
                            v1 += E[(size_t)row*lde + col + 1];
                        }
                        *reinterpret_cast<float2*>(C + (size_t)row*ldc + col) =
                            make_float2(v0, v1);
                    }
                }
            }
        }
    }
}

// ---------------- depthwise causal conv (K=4) + SiLU -> fp32 + splits ----------------
__global__ __launch_bounds__(256) void conv_silu_k(
    const float* __restrict__ xp, const float* __restrict__ cw,
    float* __restrict__ u, __nv_bfloat16* __restrict__ uh, __nv_bfloat16* __restrict__ ul)
{
    int idx = blockIdx.x*blockDim.x + threadIdx.x;
    if (idx >= TOK*INNER) return;
    int c = idx % INNER;
    int t = idx / INNER;
    int s = t & (SEQ-1);
    const float* bp = xp + (size_t)t*XPW + c;
    float w0 = cw[c*4+0], w1 = cw[c*4+1], w2 = cw[c*4+2], w3 = cw[c*4+3];
    float acc = w3 * bp[0];
    if (s >= 1) acc = fmaf(w2, bp[-(ptrdiff_t)XPW],     acc);
    if (s >= 2) acc = fmaf(w1, bp[-(ptrdiff_t)(2*XPW)], acc);
    if (s >= 3) acc = fmaf(w0, bp[-(ptrdiff_t)(3*XPW)], acc);
    float v = acc / (1.f + __expf(-acc));
    u[idx] = v;
    __nv_bfloat16 h = __float2bfloat16(v);
    uh[idx] = h;
    ul[idx] = __float2bfloat16(v - __bfloat162float(h));
}

// ---------------- selective scan: thread per (channel,state), PF=8 ----------------
// block: 256 threads = 16 channels x 16 states; grid: 2 batches x 96 groups = 192
__global__ __launch_bounds__(256) void scan_kernel(
    const float* __restrict__ proj, const float* __restrict__ u,
    const float* __restrict__ A_log, const float* __restrict__ D,
    __nv_bfloat16* __restrict__ yh, __nv_bfloat16* __restrict__ yl)
{
    const int tid = threadIdx.x;
    const int n   = tid & 15;
    const int cl  = tid >> 4;                 // 0..15
    const int blk = blockIdx.x;               // 0..191
    const int b   = blk / 96;
    const int c   = (blk % 96)*16 + cl;
    const float a  = -__expf(A_log[n]);
    const float Dv = D[c];
    float h = 0.f;
    size_t rowP = (size_t)b*SEQ*PJW;
    size_t rowU = (size_t)b*SEQ*INNER;

    float bB[8], bC[8], bP[8], bU[8];
    #pragma unroll
    for (int i = 0; i < 8; i++) {
        bB[i] = proj[rowP + (size_t)i*PJW + n];
        bC[i] = proj[rowP + (size_t)i*PJW + 16 + n];
        bP[i] = proj[rowP + (size_t)i*PJW + 32 + c];
        bU[i] = u[rowU + (size_t)i*INNER + c];
    }
    #pragma unroll 8
    for (int s = 0; s < SEQ; s++) {
        const int sl = s & 7;
        float B_ = bB[sl], C_ = bC[sl], p = bP[sl], uu = bU[sl];
        if (s + 8 < SEQ) {
            size_t nP = rowP + (size_t)8*PJW;
            size_t nU = rowU + (size_t)8*INNER;
            bB[sl] = proj[nP + n];
            bC[sl] = proj[nP + 16 + n];
            bP[sl] = proj[nP + 32 + c];
            bU[sl] = u[nU + c];
        }
        float delta = (p > 20.f) ? p : __logf(1.f + __expf(p));
        float dA = __expf(delta * a);
        h = fmaf(dA, h, delta * uu * B_);
        float yv = h * C_;
        yv += __shfl_down_sync(0xffffffffu, yv, 8, 16);
        yv += __shfl_down_sync(0xffffffffu, yv, 4, 16);
        yv += __shfl_down_sync(0xffffffffu, yv, 2, 16);
        yv += __shfl_down_sync(0xffffffffu, yv, 1, 16);
        if (n == 0) {
            float outv = yv + Dv * uu;
            __nv_bfloat16 hh = __float2bfloat16(outv);
            yh[rowU + c] = hh;
            yl[rowU + c] = __float2bfloat16(outv - __bfloat162float(hh));
        }
        rowP += PJW; rowU += INNER;
    }
}

// ---------------- launch ----------------
extern "C" void kernel_launch(void* const* d_in, const int* in_sizes, int n_in,
                              void* d_out, int out_size)
{
    const float* x      = (const float*)d_in[0];
    const float* norm_w = (const float*)d_in[1];
    const float* norm_b = (const float*)d_in[2];
    const float* W_in   = (const float*)d_in[3];
    const float* conv_w = (const float*)d_in[4];
    const float* W_xprj = (const float*)d_in[5];
    const float* A_log  = (const float*)d_in[6];
    const float* D      = (const float*)d_in[7];
    const float* W_ssm  = (const float*)d_in[8];
    const float* W_out  = (const float*)d_in[9];
    float* out = (float*)d_out;

    #define SYM(v, g) void* p_##v; cudaGetSymbolAddress(&p_##v, g);
    SYM(xnh, g_xnh) SYM(xnl, g_xnl) SYM(xp, g_xp) SYM(u, g_u)
    SYM(uh, g_uh)   SYM(ul, g_ul)   SYM(pj, g_pj)
    SYM(y1h, g_y1h) SYM(y1l, g_y1l) SYM(y2h, g_y2h) SYM(y2l, g_y2l)
    SYM(Wih, g_Wih) SYM(Wil, g_Wil) SYM(Wxh, g_Wxh) SYM(Wxl, g_Wxl)
    SYM(Wsh, g_Wsh) SYM(Wsl, g_Wsl) SYM(Woh, g_Woh) SYM(Wol, g_Wol)
    #undef SYM
    typedef __nv_bfloat16 bf;

    const int SMEM = 3*32768 + 1024;
    cudaFuncSetAttribute(hgemm<0>, cudaFuncAttributeMaxDynamicSharedMemorySize, SMEM);
    cudaFuncSetAttribute(hgemm<1>, cudaFuncAttributeMaxDynamicSharedMemorySize, SMEM);
    cudaFuncSetAttribute(hgemm<2>, cudaFuncAttributeMaxDynamicSharedMemorySize, SMEM);

    dim3 tb(32, 8);
    tsplit_k<<<dim3(XPW/32,  HID/32),   tb>>>(W_in,   HID,   XPW,  XPW,  (bf*)p_Wih, (bf*)p_Wil);
    tsplit_k<<<dim3(NPADX/32,INNER/32), tb>>>(W_xprj, INNER, PJW,  NPADX,(bf*)p_Wxh, (bf*)p_Wxl);
    tsplit_k<<<dim3(INNER/32,INNER/32), tb>>>(W_ssm,  INNER, INNER,INNER,(bf*)p_Wsh, (bf*)p_Wsl);
    tsplit_k<<<dim3(HID/32,  INNER/32), tb>>>(W_out,  INNER, HID,  HID,  (bf*)p_Woh, (bf*)p_Wol);

    // 1. LayerNorm -> splits
    ln_kernel<<<TOK, 256>>>(x, norm_w, norm_b, (bf*)p_xnh, (bf*)p_xnl);

    // 2. xp = xn @ W_in  (4096 x 3072 x 768)
    hgemm<0><<<dim3(XPW/128, TOK/128), 256, SMEM>>>(
        (bf*)p_xnh, (bf*)p_xnl, (bf*)p_Wih, (bf*)p_Wil,
        (float*)p_xp, TOK, XPW, HID, XPW, nullptr, 0, 0, nullptr, nullptr);

    // 3. conv + silu -> u (fp32 + splits)
    conv_silu_k<<<(TOK*INNER + 255)/256, 256>>>(
        (float*)p_xp, conv_w, (float*)p_u, (bf*)p_uh, (bf*)p_ul);

    // 4. proj = u @ W_xproj  (4096 x 1568 x 1536)
    hgemm<0><<<dim3(NPADX/128, TOK/128), 256, SMEM>>>(
        (bf*)p_uh, (bf*)p_ul, (bf*)p_Wxh, (bf*)p_Wxl,
        (float*)p_pj, TOK, PJW, INNER, PJW, nullptr, 0, 0, nullptr, nullptr);

    // 5. selective scan -> y1 splits (includes +D*u)
    scan_kernel<<<192, 256>>>((float*)p_pj, (float*)p_u, A_log, D,
                              (bf*)p_y1h, (bf*)p_y1l);

    // 6. y2 = (y1 @ W_ssm_out) * silu(gate) -> splits
    hgemm<1><<<dim3(INNER/128, TOK/128), 256, SMEM>>>(
        (bf*)p_y1h, (bf*)p_y1l, (bf*)p_Wsh, (bf*)p_Wsl,
        nullptr, TOK, INNER, INNER, INNER,
        (float*)p_xp, XPW, INNER, (bf*)p_y2h, (bf*)p_y2l);

    // 7. out = y2 @ W_out + x
    hgemm<2><<<dim3(HID/128, TOK/128), 256, SMEM>>>(
        (bf*)p_y2h, (bf*)p_y2l, (bf*)p_Woh, (bf*)p_Wol,
        out, TOK, HID, INNER, HID, x, HID, 0, nullptr, nullptr);
}

// round 13
// speedup vs baseline: 3.3042x; 1.0528x over previous
#include <cuda_runtime.h>
#include <cuda_bf16.h>
#include <cstdint>
#include <math.h>

#define BATCH 2
#define SEQ   2048
#define TOK   (BATCH*SEQ)        // 4096
#define HID   768
#define INNER 1536
#define NSTATE 16
#define XPW   (2*INNER)          // 3072
#define PJW   (2*NSTATE+INNER)   // 1568
#define NPADX 1664               // PJW padded to multiple of 128

// ---------------- scratch (device globals; allocation-free) ----------------
__device__ __nv_bfloat16 g_xnh[TOK*HID], g_xnl[TOK*HID];
__device__ float         g_xp [TOK*XPW];
__device__ float         g_u  [TOK*INNER];
__device__ __nv_bfloat16 g_uh [TOK*INNER], g_ul [TOK*INNER];
__device__ float         g_pj [TOK*PJW];
__device__ __nv_bfloat16 g_y1h[TOK*INNER], g_y1l[TOK*INNER];
__device__ __nv_bfloat16 g_y2h[TOK*INNER], g_y2l[TOK*INNER];
// transposed + split weights: [Npad rows, K cols] bf16
__device__ __nv_bfloat16 g_Wih[XPW*HID],     g_Wil[XPW*HID];
__device__ __nv_bfloat16 g_Wxh[NPADX*INNER], g_Wxl[NPADX*INNER];
__device__ __nv_bfloat16 g_Wsh[INNER*INNER], g_Wsl[INNER*INNER];
__device__ __nv_bfloat16 g_Woh[HID*INNER],   g_Wol[HID*INNER];

// ---------------- helpers ----------------
__device__ __forceinline__ uint32_t smaddr(const void* p){
    uint32_t r;
    asm("{ .reg .u64 t; cvta.to.shared.u64 t, %1; cvt.u32.u64 %0, t; }"
        : "=r"(r) : "l"(p));
    return r;
}
__device__ __forceinline__ void cp16(uint32_t s, const void* g){
    asm volatile("cp.async.cg.shared.global [%0], [%1], 16;" :: "r"(s), "l"(g));
}
__device__ __forceinline__ void ldm4(uint32_t& r0, uint32_t& r1,
                                     uint32_t& r2, uint32_t& r3, uint32_t a){
    asm volatile("ldmatrix.sync.aligned.m8n8.x4.shared.b16 {%0,%1,%2,%3}, [%4];"
                 : "=r"(r0), "=r"(r1), "=r"(r2), "=r"(r3) : "r"(a));
}
__device__ __forceinline__ void mma16816(float* d, const uint32_t* a,
                                         const uint32_t* b){
    asm volatile("mma.sync.aligned.m16n8k16.row.col.f32.bf16.bf16.f32 "
                 "{%0,%1,%2,%3}, {%4,%5,%6,%7}, {%8,%9}, {%0,%1,%2,%3};"
                 : "+f"(d[0]), "+f"(d[1]), "+f"(d[2]), "+f"(d[3])
                 : "r"(a[0]), "r"(a[1]), "r"(a[2]), "r"(a[3]),
                   "r"(b[0]), "r"(b[1]));
}

// ---------------- weight transpose + split:  W[K,N] -> Th/Tl[Npad,K] ----------------
__global__ __launch_bounds__(256) void tsplit_k(
    const float* __restrict__ W, int K, int N, int Npad,
    __nv_bfloat16* __restrict__ Th, __nv_bfloat16* __restrict__ Tl)
{
    __shared__ float t[32][33];
    int k0 = blockIdx.y*32, n0 = blockIdx.x*32;
    int tx = threadIdx.x, ty = threadIdx.y;   // (32,8)
    #pragma unroll
    for (int i = 0; i < 32; i += 8) {
        int k = k0 + ty + i;
        float v = (n0 + tx < N) ? W[(size_t)k*N + n0 + tx] : 0.f;
        t[ty+i][tx] = v;
    }
    __syncthreads();
    #pragma unroll
    for (int i = 0; i < 32; i += 8) {
        int n = n0 + ty + i;
        float v = t[tx][ty+i];
        __nv_bfloat16 h = __float2bfloat16(v);
        Th[(size_t)n*K + k0 + tx] = h;
        Tl[(size_t)n*K + k0 + tx] = __float2bfloat16(v - __bfloat162float(h));
    }
}

// ---------------- LayerNorm -> bf16 hi/lo splits ----------------
__global__ __launch_bounds__(256) void ln_kernel(
    const float* __restrict__ x, const float* __restrict__ w,
    const float* __restrict__ b,
    __nv_bfloat16* __restrict__ oh, __nv_bfloat16* __restrict__ ol)
{
    int t = blockIdx.x;
    const float* xr = x + (size_t)t*HID;
    float s = 0.f, s2 = 0.f;
    for (int i = threadIdx.x; i < HID; i += 256) {
        float v = xr[i]; s += v; s2 += v*v;
    }
    __shared__ float r0[32], r1[32];
    #pragma unroll
    for (int off = 16; off > 0; off >>= 1) {
        s  += __shfl_down_sync(0xffffffffu, s,  off);
        s2 += __shfl_down_sync(0xffffffffu, s2, off);
    }
    int wid = threadIdx.x >> 5, lid = threadIdx.x & 31;
    if (lid == 0) { r0[wid] = s; r1[wid] = s2; }
    __syncthreads();
    if (wid == 0) {
        s  = (lid < 8) ? r0[lid] : 0.f;
        s2 = (lid < 8) ? r1[lid] : 0.f;
        #pragma unroll
        for (int off = 4; off > 0; off >>= 1) {
            s  += __shfl_down_sync(0xffffffffu, s,  off);
            s2 += __shfl_down_sync(0xffffffffu, s2, off);
        }
        if (lid == 0) { r0[0] = s; r1[0] = s2; }
    }
    __syncthreads();
    float mu  = r0[0] * (1.f/HID);
    float var = r1[0] * (1.f/HID) - mu*mu;
    float inv = rsqrtf(var + 1e-5f);
    for (int i = threadIdx.x; i < HID; i += 256) {
        float v = (xr[i] - mu) * inv * w[i] + b[i];
        __nv_bfloat16 h = __float2bfloat16(v);
        oh[(size_t)t*HID + i] = h;
        ol[(size_t)t*HID + i] = __float2bfloat16(v - __bfloat162float(h));
    }
}

// ---------------- split-bf16 HMMA GEMM, fused 3-product chunks ----------------
// C[M,N] = A @ B^T (B pre-transposed [Npad,K]); Ah*Bh + Ah*Bl + Al*Bh.
// Per 32-K chunk: ONE stage holds Ah|Al|Bh|Bl (4 x 8KB tiles); all three
// products computed from it (a-regs reloaded Ah->Al, b-regs stay live).
// CTA 128x128, 8 warps (warp tile 64x32), 3-stage cp.async, 2 CTAs/SM.
// EP=0: fp32 C; EP=1: v*=silu(E[..eoff+col]) -> bf16 splits; EP=2: v+=E -> fp32.
template<int EP>
__global__ __launch_bounds__(256, 2) void hgemm(
    const __nv_bfloat16* __restrict__ Ah, const __nv_bfloat16* __restrict__ Al,
    const __nv_bfloat16* __restrict__ Bh, const __nv_bfloat16* __restrict__ Bl,
    float* __restrict__ C, int M, int N, int K, int ldc,
    const float* __restrict__ E, int lde, int eoff,
    __nv_bfloat16* __restrict__ Ch, __nv_bfloat16* __restrict__ Cl)
{
    extern __shared__ __align__(16) char dsm[];
    const int tid  = threadIdx.x;
    const int wid  = tid >> 5, lane = tid & 31;
    const int wm   = wid >> 2, wn = wid & 3;      // 2 x 4 warps
    const int bm   = blockIdx.y*128, bn = blockIdx.x*128;

    uint32_t dyn  = smaddr(dsm);
    uint32_t base = (dyn + 1023u) & ~1023u;

    const int NC = K >> 5;                        // 32-K chunks

    float acc[4][4][4];
    #pragma unroll
    for (int i = 0; i < 4; i++)
        #pragma unroll
        for (int j = 0; j < 4; j++)
            #pragma unroll
            for (int r = 0; r < 4; r++) acc[i][j][r] = 0.f;

    // stage layout: [Ah 8KB][Al 8KB][Bh 8KB][Bl 8KB]; rows are 64B, SW64 swizzle
    auto load_stage = [&](int st, int c){
        int kk = c << 5;
        uint32_t s0 = base + st*32768;
        #pragma unroll
        for (int half = 0; half < 2; half++) {
            int q  = half*256 + tid;              // 0..511
            int r  = q >> 2, c16 = q & 3;
            uint32_t off = (uint32_t)(r*64 + c16*16);
            off ^= ((off >> 3) & 0x30);
            size_t gA = (size_t)(bm + r)*K + kk + c16*8;
            size_t gB = (size_t)(bn + r)*K + kk + c16*8;
            cp16(s0 +         off, Ah + gA);
            cp16(s0 +  8192 + off, Al + gA);
            cp16(s0 + 16384 + off, Bh + gB);
            cp16(s0 + 24576 + off, Bl + gB);
        }
    };

    auto compute = [&](int st){
        uint32_t sAh = base + st*32768;
        uint32_t sAl = sAh + 8192;
        uint32_t sBh = sAh + 16384;
        uint32_t sBl = sAh + 24576;
        #pragma unroll
        for (int ks = 0; ks < 2; ks++) {
            uint32_t a[4][4], bh[4][2], bl[4][2];
            #pragma unroll
            for (int mt = 0; mt < 4; mt++) {
                uint32_t row = wm*64 + mt*16 + (lane & 15);
                uint32_t off = row*64 + ks*32 + ((lane >> 4) & 1)*16;
                off ^= ((off >> 3) & 0x30);
                ldm4(a[mt][0], a[mt][1], a[mt][2], a[mt][3], sAh + off);
            }
            #pragma unroll
            for (int nh = 0; nh < 2; nh++) {
                uint32_t row = wn*32 + nh*16 + (lane & 7) + ((lane >> 4) & 1)*8;
                uint32_t off = row*64 + ks*32 + ((lane >> 3) & 1)*16;
                off ^= ((off >> 3) & 0x30);
                ldm4(bh[nh*2][0], bh[nh*2][1], bh[nh*2+1][0], bh[nh*2+1][1], sBh + off);
                ldm4(bl[nh*2][0], bl[nh*2][1], bl[nh*2+1][0], bl[nh*2+1][1], sBl + off);
            }
            // Ah*Bh and Ah*Bl
            #pragma unroll
            for (int mt = 0; mt < 4; mt++)
                #pragma unroll
                for (int nt = 0; nt < 4; nt++) {
                    mma16816(acc[mt][nt], a[mt], bh[nt]);
                    mma16816(acc[mt][nt], a[mt], bl[nt]);
                }
            // reload a <- Al (reuse registers), then Al*Bh
            #pragma unroll
            for (int mt = 0; mt < 4; mt++) {
                uint32_t row = wm*64 + mt*16 + (lane & 15);
                uint32_t off = row*64 + ks*32 + ((lane >> 4) & 1)*16;
                off ^= ((off >> 3) & 0x30);
                ldm4(a[mt][0], a[mt][1], a[mt][2], a[mt][3], sAl + off);
            }
            #pragma unroll
            for (int mt = 0; mt < 4; mt++)
                #pragma unroll
                for (int nt = 0; nt < 4; nt++)
                    mma16816(acc[mt][nt], a[mt], bh[nt]);
        }
    };

    load_stage(0, 0);
    asm volatile("cp.async.commit_group;");
    load_stage(1, 1);
    asm volatile("cp.async.commit_group;");
    int st = 0, ld = 2;
    for (int c = 0; c < NC; c++) {
        asm volatile("cp.async.wait_group 1;");
        __syncthreads();
        if (c + 2 < NC) load_stage(ld, c + 2);
        asm volatile("cp.async.commit_group;");
        compute(st);
        st = (st == 2) ? 0 : st + 1;
        ld = (ld == 2) ? 0 : ld + 1;
    }

    // ---- epilogue ----
    #pragma unroll
    for (int mt = 0; mt < 4; mt++) {
        #pragma unroll
        for (int half = 0; half < 2; half++) {
            int row = bm + wm*64 + mt*16 + (lane >> 2) + half*8;
            #pragma unroll
            for (int nt = 0; nt < 4; nt++) {
                int col = bn + wn*32 + nt*8 + (lane & 3)*2;
                if (col < N) {
                    float v0 = acc[mt][nt][half*2 + 0];
                    float v1 = acc[mt][nt][half*2 + 1];
                    if constexpr (EP == 1) {
                        float g0 = E[(size_t)row*lde + eoff + col];
                        float g1 = E[(size_t)row*lde + eoff + col + 1];
                        v0 *= g0 / (1.f + __expf(-g0));
                        v1 *= g1 / (1.f + __expf(-g1));
                        __nv_bfloat16 h0 = __float2bfloat16(v0);
                        __nv_bfloat16 h1 = __float2bfloat16(v1);
                        Ch[(size_t)row*ldc + col]   = h0;
                        Ch[(size_t)row*ldc + col+1] = h1;
                        Cl[(size_t)row*ldc + col]   = __float2bfloat16(v0 - __bfloat162float(h0));
                        Cl[(size_t)row*ldc + col+1] = __float2bfloat16(v1 - __bfloat162float(h1));
                    } else {
                        if constexpr (EP == 2) {
                            v0 += E[(size_t)row*lde + col];
                            v1 += E[(size_t)row*lde + col + 1];
                        }
                        *reinterpret_cast<float2*>(C + (size_t)row*ldc + col) =
                            make_float2(v0, v1);
                    }
                }
            }
        }
    }
}

// ---------------- depthwise causal conv (K=4) + SiLU -> fp32 + splits ----------------
__global__ __launch_bounds__(256) void conv_silu_k(
    const float* __restrict__ xp, const float* __restrict__ cw,
    float* __restrict__ u, __nv_bfloat16* __restrict__ uh, __nv_bfloat16* __restrict__ ul)
{
    int idx = blockIdx.x*blockDim.x + threadIdx.x;
    if (idx >= TOK*INNER) return;
    int c = idx % INNER;
    int t = idx / INNER;
    int s = t & (SEQ-1);
    const float* bp = xp + (size_t)t*XPW + c;
    float w0 = cw[c*4+0], w1 = cw[c*4+1], w2 = cw[c*4+2], w3 = cw[c*4+3];
    float acc = w3 * bp[0];
    if (s >= 1) acc = fmaf(w2, bp[-(ptrdiff_t)XPW],     acc);
    if (s >= 2) acc = fmaf(w1, bp[-(ptrdiff_t)(2*XPW)], acc);
    if (s >= 3) acc = fmaf(w0, bp[-(ptrdiff_t)(3*XPW)], acc);
    float v = acc / (1.f + __expf(-acc));
    u[idx] = v;
    __nv_bfloat16 h = __float2bfloat16(v);
    uh[idx] = h;
    ul[idx] = __float2bfloat16(v - __bfloat162float(h));
}

// ---------------- selective scan: thread per (channel,state), PF=8 ----------------
__global__ __launch_bounds__(256) void scan_kernel(
    const float* __restrict__ proj, const float* __restrict__ u,
    const float* __restrict__ A_log, const float* __restrict__ D,
    __nv_bfloat16* __restrict__ yh, __nv_bfloat16* __restrict__ yl)
{
    const int tid = threadIdx.x;
    const int n   = tid & 15;
    const int cl  = tid >> 4;                 // 0..15
    const int blk = blockIdx.x;               // 0..191
    const int b   = blk / 96;
    const int c   = (blk % 96)*16 + cl;
    const float a  = -__expf(A_log[n]);
    const float Dv = D[c];
    float h = 0.f;
    size_t rowP = (size_t)b*SEQ*PJW;
    size_t rowU = (size_t)b*SEQ*INNER;

    float bB[8], bC[8], bP[8], bU[8];
    #pragma unroll
    for (int i = 0; i < 8; i++) {
        bB[i] = proj[rowP + (size_t)i*PJW + n];
        bC[i] = proj[rowP + (size_t)i*PJW + 16 + n];
        bP[i] = proj[rowP + (size_t)i*PJW + 32 + c];
        bU[i] = u[rowU + (size_t)i*INNER + c];
    }
    #pragma unroll 8
    for (int s = 0; s < SEQ; s++) {
        const int sl = s & 7;
        float B_ = bB[sl], C_ = bC[sl], p = bP[sl], uu = bU[sl];
        if (s + 8 < SEQ) {
            size_t nP = rowP + (size_t)8*PJW;
            size_t nU = rowU + (size_t)8*INNER;
            bB[sl] = proj[nP + n];
            bC[sl] = proj[nP + 16 + n];
            bP[sl] = proj[nP + 32 + c];
            bU[sl] = u[nU + c];
        }
        float delta = (p > 20.f) ? p : __logf(1.f + __expf(p));
        float dA = __expf(delta * a);
        h = fmaf(dA, h, delta * uu * B_);
        float yv = h * C_;
        yv += __shfl_down_sync(0xffffffffu, yv, 8, 16);
        yv += __shfl_down_sync(0xffffffffu, yv, 4, 16);
        yv += __shfl_down_sync(0xffffffffu, yv, 2, 16);
        yv += __shfl_down_sync(0xffffffffu, yv, 1, 16);
        if (n == 0) {
            float outv = yv + Dv * uu;
            __nv_bfloat16 hh = __float2bfloat16(outv);
            yh[rowU + c] = hh;
            yl[rowU + c] = __float2bfloat16(outv - __bfloat162float(hh));
        }
        rowP += PJW; rowU += INNER;
    }
}

// ---------------- launch ----------------
extern "C" void kernel_launch(void* const* d_in, const int* in_sizes, int n_in,
                              void* d_out, int out_size)
{
    const float* x      = (const float*)d_in[0];
    const float* norm_w = (const float*)d_in[1];
    const float* norm_b = (const float*)d_in[2];
    const float* W_in   = (const float*)d_in[3];
    const float* conv_w = (const float*)d_in[4];
    const float* W_xprj = (const float*)d_in[5];
    const float* A_log  = (const float*)d_in[6];
    const float* D      = (const float*)d_in[7];
    const float* W_ssm  = (const float*)d_in[8];
    const float* W_out  = (const float*)d_in[9];
    float* out = (float*)d_out;

    #define SYM(v, g) void* p_##v; cudaGetSymbolAddress(&p_##v, g);
    SYM(xnh, g_xnh) SYM(xnl, g_xnl) SYM(xp, g_xp) SYM(u, g_u)
    SYM(uh, g_uh)   SYM(ul, g_ul)   SYM(pj, g_pj)
    SYM(y1h, g_y1h) SYM(y1l, g_y1l) SYM(y2h, g_y2h) SYM(y2l, g_y2l)
    SYM(Wih, g_Wih) SYM(Wil, g_Wil) SYM(Wxh, g_Wxh) SYM(Wxl, g_Wxl)
    SYM(Wsh, g_Wsh) SYM(Wsl, g_Wsl) SYM(Woh, g_Woh) SYM(Wol, g_Wol)
    #undef SYM
    typedef __nv_bfloat16 bf;

    const int SMEM = 3*32768 + 1024;
    cudaFuncSetAttribute(hgemm<0>, cudaFuncAttributeMaxDynamicSharedMemorySize, SMEM);
    cudaFuncSetAttribute(hgemm<1>, cudaFuncAttributeMaxDynamicSharedMemorySize, SMEM);
    cudaFuncSetAttribute(hgemm<2>, cudaFuncAttributeMaxDynamicSharedMemorySize, SMEM);

    dim3 tb(32, 8);
    tsplit_k<<<dim3(XPW/32,  HID/32),   tb>>>(W_in,   HID,   XPW,  XPW,  (bf*)p_Wih, (bf*)p_Wil);
    tsplit_k<<<dim3(NPADX/32,INNER/32), tb>>>(W_xprj, INNER, PJW,  NPADX,(bf*)p_Wxh, (bf*)p_Wxl);
    tsplit_k<<<dim3(INNER/32,INNER/32), tb>>>(W_ssm,  INNER, INNER,INNER,(bf*)p_Wsh, (bf*)p_Wsl);
    tsplit_k<<<dim3(HID/32,  INNER/32), tb>>>(W_out,  INNER, HID,  HID,  (bf*)p_Woh, (bf*)p_Wol);

    // 1. LayerNorm -> splits
    ln_kernel<<<TOK, 256>>>(x, norm_w, norm_b, (bf*)p_xnh, (bf*)p_xnl);

    // 2. xp = xn @ W_in  (4096 x 3072 x 768)
    hgemm<0><<<dim3(XPW/128, TOK/128), 256, SMEM>>>(
        (bf*)p_xnh, (bf*)p_xnl, (bf*)p_Wih, (bf*)p_Wil,
        (float*)p_xp, TOK, XPW, HID, XPW, nullptr, 0, 0, nullptr, nullptr);

    // 3. conv + silu -> u (fp32 + splits)
    conv_silu_k<<<(TOK*INNER + 255)/256, 256>>>(
        (float*)p_xp, conv_w, (float*)p_u, (bf*)p_uh, (bf*)p_ul);

    // 4. proj = u @ W_xproj  (4096 x 1568 x 1536)
    hgemm<0><<<dim3(NPADX/128, TOK/128), 256, SMEM>>>(
        (bf*)p_uh, (bf*)p_ul, (bf*)p_Wxh, (bf*)p_Wxl,
        (float*)p_pj, TOK, PJW, INNER, PJW, nullptr, 0, 0, nullptr, nullptr);

    // 5. selective scan -> y1 splits (includes +D*u)
    scan_kernel<<<192, 256>>>((float*)p_pj, (float*)p_u, A_log, D,
                              (bf*)p_y1h, (bf*)p_y1l);

    // 6. y2 = (y1 @ W_ssm_out) * silu(gate) -> splits
    hgemm<1><<<dim3(INNER/128, TOK/128), 256, SMEM>>>(
        (bf*)p_y1h, (bf*)p_y1l, (bf*)p_Wsh, (bf*)p_Wsl,
        nullptr, TOK, INNER, INNER, INNER,
        (float*)p_xp, XPW, INNER, (bf*)p_y2h, (bf*)p_y2l);

    // 7. out = y2 @ W_out + x
    hgemm<2><<<dim3(HID/128, TOK/128), 256, SMEM>>>(
        (bf*)p_y2h, (bf*)p_y2l, (bf*)p_Woh, (bf*)p_Wol,
        out, TOK, HID, INNER, HID, x, HID, 0, nullptr, nullptr);
}